// round 5
// baseline (speedup 1.0000x reference)
#include <cuda_runtime.h>
#include <cuda_bf16.h>
#include <cstdint>
#include <math.h>

// Problem constants
#define Bn   32768
#define Nn   14
#define Ed   64
#define Cd   128
#define Mrows (Bn * 14)    // 458752 = 7168 * 64

#define WS   136           // padded bf16 row stride (272B; bank=4*row+pair, conflict-free)

// ---------------------------------------------------------------------------
// Scratch (__device__ globals; 16B-aligned wrappers for vector access)
// ---------------------------------------------------------------------------
struct __align__(16) FBuf  { float f[(size_t)Mrows * Cd]; };
struct __align__(16) WBuf  { __nv_bfloat16 h[128 * WS]; };
struct __align__(16) WlpBuf{ float f[Nn * Cd]; };

__device__ FBuf   g_buf0;                      // Hpre1 / Hpre2
__device__ FBuf   g_h1;                        // relu'd layer-1 output
__device__ WlpBuf g_wlp;                       // Wl @ Wp
__device__ float  g_c0;                        // bl @ Wp + bp
__device__ WBuf   g_w1hi, g_w1lo, g_w2hi, g_w2lo;

// ---------------------------------------------------------------------------
// Helpers
// ---------------------------------------------------------------------------
__device__ __forceinline__ void cvt_hi_lo(float f, __nv_bfloat16& hi, __nv_bfloat16& lo)
{
    hi = __float2bfloat16(f);
    lo = __float2bfloat16(f - __bfloat162float(hi));
}
__device__ __forceinline__ void cvt_hi_lo2(float f0, float f1, uint32_t& hi, uint32_t& lo)
{
    __nv_bfloat16 h0, l0, h1, l1;
    cvt_hi_lo(f0, h0, l0);
    cvt_hi_lo(f1, h1, l1);
    __nv_bfloat162 hp = __halves2bfloat162(h0, h1);
    __nv_bfloat162 lp = __halves2bfloat162(l0, l1);
    hi = *reinterpret_cast<uint32_t*>(&hp);
    lo = *reinterpret_cast<uint32_t*>(&lp);
}

__device__ __forceinline__ unsigned fkey(float x)
{
    unsigned u = __float_as_uint(x);
    return u ^ ((unsigned)(((int)u) >> 31) | 0x80000000u);
}
__device__ __forceinline__ float kinv(unsigned k)
{
    unsigned u = k ^ ((k & 0x80000000u) ? 0x80000000u : 0xFFFFFFFFu);
    return __uint_as_float(u);
}

__device__ __forceinline__ uint32_t smem_u32(const void* p)
{
    uint32_t a;
    asm("{ .reg .u64 t; cvta.to.shared.u64 t, %1; cvt.u32.u64 %0, t; }"
        : "=r"(a) : "l"(p));
    return a;
}
__device__ __forceinline__ void cp16(uint32_t dst, const void* src)
{
    asm volatile("cp.async.cg.shared.global [%0], [%1], 16;"
                 :: "r"(dst), "l"(src));
}
__device__ __forceinline__ void ldsm4(uint32_t& r0, uint32_t& r1,
                                      uint32_t& r2, uint32_t& r3, uint32_t addr)
{
    asm volatile("ldmatrix.sync.aligned.m8n8.x4.shared.b16 {%0,%1,%2,%3}, [%4];"
                 : "=r"(r0), "=r"(r1), "=r"(r2), "=r"(r3) : "r"(addr));
}

// m16n8k16 bf16 MMA (base-target HMMA)
__device__ __forceinline__ void mma16816(float* d, uint32_t a0, uint32_t a1,
                                         uint32_t a2, uint32_t a3,
                                         uint32_t b0, uint32_t b1)
{
    asm volatile(
        "mma.sync.aligned.m16n8k16.row.col.f32.bf16.bf16.f32 "
        "{%0,%1,%2,%3}, {%4,%5,%6,%7}, {%8,%9}, {%0,%1,%2,%3};"
        : "+f"(d[0]), "+f"(d[1]), "+f"(d[2]), "+f"(d[3])
        : "r"(a0), "r"(a1), "r"(a2), "r"(a3), "r"(b0), "r"(b1));
}

// ---------------------------------------------------------------------------
// Weight prep: W[k=128, n=128] row-major fp32 -> hi/lo bf16 images [n][k] padded
// ---------------------------------------------------------------------------
__global__ void prep_w_kernel(const float* __restrict__ W,
                              __nv_bfloat16* __restrict__ ohi,
                              __nv_bfloat16* __restrict__ olo)
{
    int idx = blockIdx.x * blockDim.x + threadIdx.x;
    if (idx >= 128 * 128) return;
    int n = idx >> 7, k = idx & 127;
    float w = W[k * 128 + n];
    __nv_bfloat16 hi, lo;
    cvt_hi_lo(w, hi, lo);
    ohi[n * WS + k] = hi;
    olo[n * WS + k] = lo;
}

// ---------------------------------------------------------------------------
// Collapse prediction head: wlp = Wl @ Wp, c0 = bl . Wp + bp
// ---------------------------------------------------------------------------
__global__ void wlp_kernel(const float* __restrict__ Wl,
                           const float* __restrict__ Wp,
                           const float* __restrict__ bl,
                           const float* __restrict__ bp)
{
    int idx = blockIdx.x * blockDim.x + threadIdx.x;
    if (idx < Nn * Cd) {
        const float* row = Wl + (size_t)idx * 64;
        float s = 0.f;
        #pragma unroll
        for (int j = 0; j < 64; ++j) s = fmaf(row[j], Wp[j], s);
        g_wlp.f[idx] = s;
    }
    if (idx == 0) {
        float s = bp[0];
        #pragma unroll
        for (int j = 0; j < 64; ++j) s = fmaf(bl[j], Wp[j], s);
        g_c0 = s;
    }
}

// ---------------------------------------------------------------------------
// Tensor-core GEMM: C[M,128] = A[M,128] @ W[128,128], split-bf16 (3 passes).
// M-tile 64, 256 threads (8 warps), warp tile 16x64, 2 CTAs/SM.
// smem: Ahi 17408 | Alo 17408 | Bhi 34816 | Blo 34816 = 104448 B
// ---------------------------------------------------------------------------
#define A_IMG 17408
#define B_IMG 34816
#define TG_SMEM (2 * A_IMG + 2 * B_IMG)

__global__ __launch_bounds__(256, 2) void tgemm_kernel(
    const float* __restrict__ A,
    const __nv_bfloat16* __restrict__ whi,
    const __nv_bfloat16* __restrict__ wlo,
    float* __restrict__ C)
{
    extern __shared__ __align__(16) uint8_t smem[];
    const int tid = threadIdx.x;
    const size_t row0 = (size_t)blockIdx.x * 64;

    const uint32_t sb   = smem_u32(smem);
    const uint32_t sBhi = sb + 2 * A_IMG;
    const uint32_t sBlo = sBhi + B_IMG;

    // B images via cp.async (2176 uint4 each)
    {
        const uint4* s1 = (const uint4*)whi;
        const uint4* s2 = (const uint4*)wlo;
        #pragma unroll
        for (int i = 0; i < 9; ++i) {
            int j = tid + 256 * i;
            if (j < 2176) {
                cp16(sBhi + 16 * j, s1 + j);
                cp16(sBlo + 16 * j, s2 + j);
            }
        }
        asm volatile("cp.async.commit_group;");
    }

    // A tile (64x128 fp32): load, split-convert, store hi/lo images
    {
        __nv_bfloat16* Ahi = (__nv_bfloat16*)smem;
        __nv_bfloat16* Alo = (__nv_bfloat16*)(smem + A_IMG);
        const float* Ab = A + row0 * 128;
        float4 v[8];
        #pragma unroll
        for (int it = 0; it < 8; ++it) {
            int f = tid + 256 * it;            // float4 id 0..2047
            v[it] = *(const float4*)&Ab[(f >> 5) * 128 + ((f & 31) << 2)];
        }
        #pragma unroll
        for (int it = 0; it < 8; ++it) {
            int f = tid + 256 * it;
            int row = f >> 5, c4 = (f & 31) << 2;
            uint32_t h0, l0, h1, l1;
            cvt_hi_lo2(v[it].x, v[it].y, h0, l0);
            cvt_hi_lo2(v[it].z, v[it].w, h1, l1);
            *(uint2*)&Ahi[row * WS + c4] = make_uint2(h0, h1);
            *(uint2*)&Alo[row * WS + c4] = make_uint2(l0, l1);
        }
    }
    asm volatile("cp.async.wait_group 0;");
    __syncthreads();

    const int w = tid >> 5, lane = tid & 31;
    const int mrow0 = (w >> 1) * 16;           // 4 m-blocks of 16
    const int ncol0 = (w & 1) * 64;            // 2 n-blocks of 64
    const int blk = lane >> 3, rw = lane & 7;

    // ldmatrix per-lane base addresses
    // A x4 blocks: 0:(m,k0) 1:(m+8,k0) 2:(m,k0+8) 3:(m+8,k0+8)
    const uint32_t aAddr =
        sb + ((mrow0 + rw + (blk & 1) * 8) * WS + (blk >> 1) * 8) * 2;
    // B x4 blocks (per 16-n group): 0:(n,k0) 1:(n,k0+8) 2:(n+8,k0) 3:(n+8,k0+8)
    uint32_t bAddr[4];
    #pragma unroll
    for (int grp = 0; grp < 4; ++grp)
        bAddr[grp] = sBhi +
            ((ncol0 + grp * 16 + rw + (blk >> 1) * 8) * WS + (blk & 1) * 8) * 2;

    float d[8][4];
    #pragma unroll
    for (int nb = 0; nb < 8; ++nb)
        #pragma unroll
        for (int j = 0; j < 4; ++j) d[nb][j] = 0.f;

    const uint32_t aOff[3] = { 0u, 0u, (uint32_t)A_IMG };
    const uint32_t bOff[3] = { 0u, (uint32_t)B_IMG, 0u };

    #pragma unroll 1
    for (int pass = 0; pass < 3; ++pass) {
        const uint32_t ab = aAddr + aOff[pass];
        const uint32_t bo = bOff[pass];
        #pragma unroll
        for (int k0 = 0; k0 < 128; k0 += 16) {
            uint32_t a0, a1, a2, a3;
            ldsm4(a0, a1, a2, a3, ab + k0 * 2);
            #pragma unroll
            for (int grp = 0; grp < 4; ++grp) {
                uint32_t b0, b1, b2, b3;
                ldsm4(b0, b1, b2, b3, bAddr[grp] + bo + k0 * 2);
                mma16816(d[2 * grp],     a0, a1, a2, a3, b0, b1);
                mma16816(d[2 * grp + 1], a0, a1, a2, a3, b2, b3);
            }
        }
    }

    // epilogue: float2 stores
    const int g = lane >> 2, tig = lane & 3;
    float* Cb = C + row0 * 128;
    #pragma unroll
    for (int nb = 0; nb < 8; ++nb) {
        int c = ncol0 + nb * 8 + 2 * tig;
        *(float2*)&Cb[(mrow0 + g) * 128 + c]     = make_float2(d[nb][0], d[nb][1]);
        *(float2*)&Cb[(mrow0 + g + 8) * 128 + c] = make_float2(d[nb][2], d[nb][3]);
    }
}

// ---------------------------------------------------------------------------
// GAT scatter layer: warp-per-batch. CTA = 8 warps = 8 batches.
// ---------------------------------------------------------------------------
#define GW 8

template <bool LAYER2>
__global__ __launch_bounds__(256) void gat_kernel(
    const float* __restrict__ Hpre,
    const int*   __restrict__ edges,
    const float* __restrict__ a_s,
    const float* __restrict__ a_d,
    const float* __restrict__ bias,
    float* __restrict__ out_h,
    float* __restrict__ out_pred,
    float* __restrict__ out_attn)
{
    __shared__ float    s_asn[GW][16], s_adn[GW][16], s_z[GW][16];
    __shared__ unsigned s_mk[GW][16];
    __shared__ float    s_Am[GW][200];
    __shared__ __align__(16) float s_At[GW][196];

    const int tid = threadIdx.x;
    const int w = tid >> 5, lane = tid & 31;
    const int b = blockIdx.x * GW + w;

    #pragma unroll
    for (int i = 0; i < 7; ++i) {
        int j = lane + 32 * i;
        if (j < 196) { s_Am[w][j] = 0.f; if (LAYER2) s_At[w][j] = 0.f; }
    }
    if (lane < 14) { s_mk[w][lane] = 0u; s_z[w][lane] = 0.f; }

    const float* hb = Hpre + (size_t)b * (Nn * Cd);
    float4 v[Nn];
    #pragma unroll
    for (int n = 0; n < Nn; ++n)
        v[n] = *(const float4*)&hb[n * Cd + lane * 4];
    const float4 as4 = *(const float4*)&a_s[lane * 4];
    const float4 ad4 = *(const float4*)&a_d[lane * 4];
    const float4 bi4 = *(const float4*)&bias[lane * 4];

    float pa[Nn], pd[Nn];
    #pragma unroll
    for (int n = 0; n < Nn; ++n) {
        pa[n] = v[n].x * as4.x + v[n].y * as4.y + v[n].z * as4.z + v[n].w * as4.w;
        pd[n] = v[n].x * ad4.x + v[n].y * ad4.y + v[n].z * ad4.z + v[n].w * ad4.w;
    }
    #pragma unroll
    for (int o = 16; o > 0; o >>= 1) {
        #pragma unroll
        for (int n = 0; n < Nn; ++n) {
            pa[n] += __shfl_xor_sync(0xffffffffu, pa[n], o);
            pd[n] += __shfl_xor_sync(0xffffffffu, pd[n], o);
        }
    }
    if (lane == 0) {
        #pragma unroll
        for (int n = 0; n < Nn; ++n) { s_asn[w][n] = pa[n]; s_adn[w][n] = pd[n]; }
    }
    __syncwarp();

    const int* eb = edges + (size_t)b * (Ed * 2);
    int  es_[3], ed_[3];
    float lg_[3], ev_[3];
    bool act[3];
    #pragma unroll
    for (int r = 0; r < 3; ++r) {
        int e = lane + 32 * r;
        act[r] = (e < 78);
        es_[r] = 0; ed_[r] = 0; lg_[r] = 0.f;
        if (act[r]) {
            int s, dd;
            if (e < Ed) { int2 p = *(const int2*)&eb[2 * e]; s = p.x; dd = p.y; }
            else        { s = dd = e - Ed; }
            float x = s_asn[w][s] + s_adn[w][dd];
            x = (x > 0.f) ? x : 0.2f * x;
            es_[r] = s; ed_[r] = dd; lg_[r] = x;
            atomicMax(&s_mk[w][dd], fkey(x));
        }
    }
    __syncwarp();
    #pragma unroll
    for (int r = 0; r < 3; ++r) {
        if (act[r]) {
            float m = kinv(s_mk[w][ed_[r]]);
            ev_[r] = expf(lg_[r] - m);
            atomicAdd(&s_z[w][ed_[r]], ev_[r]);
        }
    }
    __syncwarp();
    #pragma unroll
    for (int r = 0; r < 3; ++r) {
        if (act[r]) {
            float al = ev_[r] / s_z[w][ed_[r]];
            atomicAdd(&s_Am[w][ed_[r] * Nn + es_[r]], al);
            if (LAYER2) s_At[w][es_[r] * Nn + ed_[r]] = al;
        }
    }
    __syncwarp();

    if (!LAYER2) {
        float* ob = out_h + (size_t)b * (Nn * Cd);
        #pragma unroll
        for (int n = 0; n < Nn; ++n) {
            float4 acc = bi4;
            #pragma unroll
            for (int s = 0; s < Nn; ++s) {
                float am = s_Am[w][n * Nn + s];
                acc.x = fmaf(am, v[s].x, acc.x);
                acc.y = fmaf(am, v[s].y, acc.y);
                acc.z = fmaf(am, v[s].z, acc.z);
                acc.w = fmaf(am, v[s].w, acc.w);
            }
            acc.x = fmaxf(acc.x, 0.f); acc.y = fmaxf(acc.y, 0.f);
            acc.z = fmaxf(acc.z, 0.f); acc.w = fmaxf(acc.w, 0.f);
            *(float4*)&ob[n * Cd + lane * 4] = acc;
        }
    } else {
        float p = 0.f;
        #pragma unroll
        for (int n = 0; n < Nn; ++n) {
            float4 acc = bi4;
            #pragma unroll
            for (int s = 0; s < Nn; ++s) {
                float am = s_Am[w][n * Nn + s];
                acc.x = fmaf(am, v[s].x, acc.x);
                acc.y = fmaf(am, v[s].y, acc.y);
                acc.z = fmaf(am, v[s].z, acc.z);
                acc.w = fmaf(am, v[s].w, acc.w);
            }
            float4 wv = *(const float4*)&g_wlp.f[n * Cd + lane * 4];
            p += acc.x * wv.x + acc.y * wv.y + acc.z * wv.z + acc.w * wv.w;
        }
        #pragma unroll
        for (int o = 16; o > 0; o >>= 1)
            p += __shfl_xor_sync(0xffffffffu, p, o);
        if (lane == 0)
            out_pred[b] = 1.f / (1.f + expf(-(p + g_c0)));
        __syncwarp();
        float* ab = out_attn + (size_t)b * (Nn * Nn);
        #pragma unroll
        for (int i = 0; i < 2; ++i) {
            int j = lane + 32 * i;
            if (j < 49)
                *(float4*)&ab[4 * j] = *(const float4*)&s_At[w][4 * j];
        }
    }
}

// ---------------------------------------------------------------------------
extern "C" void kernel_launch(void* const* d_in, const int* in_sizes, int n_in,
                              void* d_out, int out_size)
{
    const float* feature = (const float*)d_in[0];
    const int*   edges   = (const int*)  d_in[1];
    const float* W1      = (const float*)d_in[2];
    const float* a_s1    = (const float*)d_in[3];
    const float* a_d1    = (const float*)d_in[4];
    const float* b1      = (const float*)d_in[5];
    const float* W2      = (const float*)d_in[6];
    const float* a_s2    = (const float*)d_in[7];
    const float* a_d2    = (const float*)d_in[8];
    const float* b2      = (const float*)d_in[9];
    const float* Wl      = (const float*)d_in[10];
    const float* bl      = (const float*)d_in[11];
    const float* Wp      = (const float*)d_in[12];
    const float* bp      = (const float*)d_in[13];

    float* out  = (float*)d_out;
    float* pred = out;            // [B]
    float* attn = out + Bn;       // [B,N,N]

    void *p_buf0, *p_h1, *p_w1h, *p_w1l, *p_w2h, *p_w2l;
    cudaGetSymbolAddress(&p_buf0, g_buf0);
    cudaGetSymbolAddress(&p_h1,   g_h1);
    cudaGetSymbolAddress(&p_w1h,  g_w1hi);
    cudaGetSymbolAddress(&p_w1l,  g_w1lo);
    cudaGetSymbolAddress(&p_w2h,  g_w2hi);
    cudaGetSymbolAddress(&p_w2l,  g_w2lo);
    float* buf0 = (float*)p_buf0;
    float* h1   = (float*)p_h1;
    __nv_bfloat16* w1h = (__nv_bfloat16*)p_w1h;
    __nv_bfloat16* w1l = (__nv_bfloat16*)p_w1l;
    __nv_bfloat16* w2h = (__nv_bfloat16*)p_w2h;
    __nv_bfloat16* w2l = (__nv_bfloat16*)p_w2l;

    cudaFuncSetAttribute(tgemm_kernel,
                         cudaFuncAttributeMaxDynamicSharedMemorySize, TG_SMEM);

    // 0. pre-convert weights into padded bf16 hi/lo images
    prep_w_kernel<<<128, 128>>>(W1, w1h, w1l);
    prep_w_kernel<<<128, 128>>>(W2, w2h, w2l);

    // 1. collapse prediction head
    wlp_kernel<<<14, 128>>>(Wl, Wp, bl, bp);

    // 2. Hpre1 = feature @ W1  (HMMA split-bf16)
    tgemm_kernel<<<Mrows / 64, 256, TG_SMEM>>>(feature, w1h, w1l, buf0);

    // 3. GAT layer 1 (relu epilogue)
    gat_kernel<false><<<Bn / GW, 256>>>(buf0, edges, a_s1, a_d1, b1, h1, nullptr, nullptr);

    // 4. Hpre2 = h1 @ W2
    tgemm_kernel<<<Mrows / 64, 256, TG_SMEM>>>(h1, w2h, w2l, buf0);

    // 5. GAT layer 2 + attn + fused sigmoid head
    gat_kernel<true><<<Bn / GW, 256>>>(buf0, edges, a_s2, a_d2, b2, nullptr, pred, attn);
}

// round 8
// speedup vs baseline: 1.0720x; 1.0720x over previous
#include <cuda_runtime.h>
#include <cuda_bf16.h>
#include <cstdint>
#include <math.h>

// Problem constants
#define Bn   32768
#define Nn   14
#define Ed   64
#define Cd   128
#define Mrows (Bn * 14)    // 458752
#define NT   (Mrows / 64)  // 7168 M-tiles of 64 rows
#define GRID_G 296         // persistent CTAs: 2 per SM x 148 SMs

#define WS   136           // padded bf16 row stride (272B; conflict-free ldsm)

// ---------------------------------------------------------------------------
// Scratch
// ---------------------------------------------------------------------------
struct __align__(16) FBuf  { float f[(size_t)Mrows * Cd]; };
struct __align__(16) WBuf  { __nv_bfloat16 h[128 * WS]; };
struct __align__(16) WlpBuf{ float f[Nn * Cd]; };

__device__ FBuf   g_buf0;                      // Hpre1 / Hpre2
__device__ FBuf   g_h1;                        // relu'd layer-1 output
__device__ WlpBuf g_wlp;                       // Wl @ Wp
__device__ float  g_c0;                        // bl @ Wp + bp
__device__ WBuf   g_w1hi, g_w1lo, g_w2hi, g_w2lo;

// ---------------------------------------------------------------------------
// Helpers
// ---------------------------------------------------------------------------
__device__ __forceinline__ void cvt_hi_lo(float f, __nv_bfloat16& hi, __nv_bfloat16& lo)
{
    hi = __float2bfloat16(f);
    lo = __float2bfloat16(f - __bfloat162float(hi));
}
__device__ __forceinline__ void cvt_hi_lo2(float f0, float f1, uint32_t& hi, uint32_t& lo)
{
    __nv_bfloat16 h0, l0, h1, l1;
    cvt_hi_lo(f0, h0, l0);
    cvt_hi_lo(f1, h1, l1);
    __nv_bfloat162 hp = __halves2bfloat162(h0, h1);
    __nv_bfloat162 lp = __halves2bfloat162(l0, l1);
    hi = *reinterpret_cast<uint32_t*>(&hp);
    lo = *reinterpret_cast<uint32_t*>(&lp);
}

__device__ __forceinline__ unsigned fkey(float x)
{
    unsigned u = __float_as_uint(x);
    return u ^ ((unsigned)(((int)u) >> 31) | 0x80000000u);
}
__device__ __forceinline__ float kinv(unsigned k)
{
    unsigned u = k ^ ((k & 0x80000000u) ? 0x80000000u : 0xFFFFFFFFu);
    return __uint_as_float(u);
}

__device__ __forceinline__ uint32_t smem_u32(const void* p)
{
    uint32_t a;
    asm("{ .reg .u64 t; cvta.to.shared.u64 t, %1; cvt.u32.u64 %0, t; }"
        : "=r"(a) : "l"(p));
    return a;
}
__device__ __forceinline__ void cp16(uint32_t dst, const void* src)
{
    asm volatile("cp.async.cg.shared.global [%0], [%1], 16;"
                 :: "r"(dst), "l"(src));
}
__device__ __forceinline__ void ldsm4(uint32_t& r0, uint32_t& r1,
                                      uint32_t& r2, uint32_t& r3, uint32_t addr)
{
    asm volatile("ldmatrix.sync.aligned.m8n8.x4.shared.b16 {%0,%1,%2,%3}, [%4];"
                 : "=r"(r0), "=r"(r1), "=r"(r2), "=r"(r3) : "r"(addr));
}

// m16n8k16 bf16 MMA (base-target HMMA)
__device__ __forceinline__ void mma16816(float* d, uint32_t a0, uint32_t a1,
                                         uint32_t a2, uint32_t a3,
                                         uint32_t b0, uint32_t b1)
{
    asm volatile(
        "mma.sync.aligned.m16n8k16.row.col.f32.bf16.bf16.f32 "
        "{%0,%1,%2,%3}, {%4,%5,%6,%7}, {%8,%9}, {%0,%1,%2,%3};"
        : "+f"(d[0]), "+f"(d[1]), "+f"(d[2]), "+f"(d[3])
        : "r"(a0), "r"(a1), "r"(a2), "r"(a3), "r"(b0), "r"(b1));
}

// ---------------------------------------------------------------------------
// Weight prep: W[k=128, n=128] row-major fp32 -> hi/lo bf16 images [n][k] padded
// ---------------------------------------------------------------------------
__global__ void prep_w_kernel(const float* __restrict__ W,
                              __nv_bfloat16* __restrict__ ohi,
                              __nv_bfloat16* __restrict__ olo)
{
    int idx = blockIdx.x * blockDim.x + threadIdx.x;
    if (idx >= 128 * 128) return;
    int n = idx >> 7, k = idx & 127;
    float w = W[k * 128 + n];
    __nv_bfloat16 hi, lo;
    cvt_hi_lo(w, hi, lo);
    ohi[n * WS + k] = hi;
    olo[n * WS + k] = lo;
}

// ---------------------------------------------------------------------------
// Collapse prediction head: wlp = Wl @ Wp, c0 = bl . Wp + bp
// ---------------------------------------------------------------------------
__global__ void wlp_kernel(const float* __restrict__ Wl,
                           const float* __restrict__ Wp,
                           const float* __restrict__ bl,
                           const float* __restrict__ bp)
{
    int idx = blockIdx.x * blockDim.x + threadIdx.x;
    if (idx < Nn * Cd) {
        const float* row = Wl + (size_t)idx * 64;
        float s = 0.f;
        #pragma unroll
        for (int j = 0; j < 64; ++j) s = fmaf(row[j], Wp[j], s);
        g_wlp.f[idx] = s;
    }
    if (idx == 0) {
        float s = bp[0];
        #pragma unroll
        for (int j = 0; j < 64; ++j) s = fmaf(bl[j], Wp[j], s);
        g_c0 = s;
    }
}

// ---------------------------------------------------------------------------
// Persistent tensor-core GEMM: C[M,128] = A[M,128] @ W[128,128], split-bf16.
// Grid = 296 (2 CTAs/SM). B hi/lo loaded ONCE per CTA; loop over M=64 tiles
// with register-prefetched A (LDG hidden under previous tile's MMA).
// smem: Ahi 17408 | Alo 17408 | Bhi 34816 | Blo 34816 = 104448 (2/SM fits)
// Warp tile 32x32 (2m x 4n warp grid): 4 ldsm.x4 + 8 mma per k-step.
// ---------------------------------------------------------------------------
#define A_IMG 17408
#define B_IMG 34816
#define TG_SMEM (2 * A_IMG + 2 * B_IMG)

__global__ __launch_bounds__(256, 2) void tgemm_kernel(
    const float* __restrict__ A,
    const __nv_bfloat16* __restrict__ whi,
    const __nv_bfloat16* __restrict__ wlo,
    float* __restrict__ C)
{
    extern __shared__ __align__(16) uint8_t smem[];
    const int tid = threadIdx.x;

    const uint32_t sb   = smem_u32(smem);
    const uint32_t sBhi = sb + 2 * A_IMG;
    __nv_bfloat16* Ahi = (__nv_bfloat16*)smem;
    __nv_bfloat16* Alo = (__nv_bfloat16*)(smem + A_IMG);

    // B images via cp.async, once per persistent CTA (2176 uint4 each)
    {
        const uint4* s1 = (const uint4*)whi;
        const uint4* s2 = (const uint4*)wlo;
        #pragma unroll
        for (int i = 0; i < 9; ++i) {
            int j = tid + 256 * i;
            if (j < 2176) {
                cp16(sBhi + 16 * j, s1 + j);
                cp16(sBhi + B_IMG + 16 * j, s2 + j);
            }
        }
        asm volatile("cp.async.commit_group;");
    }

    // warp/lane mapping
    const int w = tid >> 5, lane = tid & 31;
    const int m0 = (w >> 2) * 32;              // 2 m-warp rows
    const int n0 = (w & 3) * 32;               // 4 n-warp cols
    const int blk = lane >> 3, rw = lane & 7;

    // ldmatrix base addresses
    // A x4 blocks: 0:(r,k0) 1:(r+8,k0) 2:(r,k0+8) 3:(r+8,k0+8)
    // B x4 blocks: 0:(n,k0) 1:(n,k0+8) 2:(n+8,k0) 3:(n+8,k0+8)
    const uint32_t aA0 = sb + ((m0 + rw + (blk & 1) * 8) * WS + (blk >> 1) * 8) * 2;
    const uint32_t aA1 = aA0 + 16 * WS * 2;
    const uint32_t bA0 = sBhi + ((n0 + rw + (blk >> 1) * 8) * WS + (blk & 1) * 8) * 2;
    const uint32_t bA1 = bA0 + 16 * WS * 2;

    const uint32_t aO[3] = { 0u, 0u, (uint32_t)A_IMG };
    const uint32_t bO[3] = { 0u, (uint32_t)B_IMG, 0u };

    // A tile staging registers (8 float4 / thread = one 64x128 fp32 tile)
    float4 v[8];

    // prologue: load + convert tile0
    int tile = blockIdx.x;
    {
        const float* Ab = A + (size_t)tile * 64 * 128;
        #pragma unroll
        for (int it = 0; it < 8; ++it) {
            int f = tid + 256 * it;
            v[it] = *(const float4*)&Ab[(f >> 5) * 128 + ((f & 31) << 2)];
        }
        #pragma unroll
        for (int it = 0; it < 8; ++it) {
            int f = tid + 256 * it;
            int row = f >> 5, c4 = (f & 31) << 2;
            uint32_t h0, l0, h1, l1;
            cvt_hi_lo2(v[it].x, v[it].y, h0, l0);
            cvt_hi_lo2(v[it].z, v[it].w, h1, l1);
            *(uint2*)&Ahi[row * WS + c4] = make_uint2(h0, h1);
            *(uint2*)&Alo[row * WS + c4] = make_uint2(l0, l1);
        }
    }
    asm volatile("cp.async.wait_group 0;");
    __syncthreads();

    while (true) {
        const int next = tile + GRID_G;
        const bool have_next = (next < NT);

        // prefetch next A tile into registers (hidden under MMA below)
        if (have_next) {
            const float* Ab = A + (size_t)next * 64 * 128;
            #pragma unroll
            for (int it = 0; it < 8; ++it) {
                int f = tid + 256 * it;
                v[it] = *(const float4*)&Ab[(f >> 5) * 128 + ((f & 31) << 2)];
            }
        }

        // MMA: 3 passes x 8 k-steps
        float d[2][4][4];
        #pragma unroll
        for (int mb = 0; mb < 2; ++mb)
            #pragma unroll
            for (int nb = 0; nb < 4; ++nb)
                #pragma unroll
                for (int j = 0; j < 4; ++j) d[mb][nb][j] = 0.f;

        #pragma unroll 1
        for (int pass = 0; pass < 3; ++pass) {
            const uint32_t ao = aO[pass], bo = bO[pass];
            #pragma unroll
            for (int k0 = 0; k0 < 128; k0 += 16) {
                uint32_t a0, a1, a2, a3, a4, a5, a6, a7;
                ldsm4(a0, a1, a2, a3, aA0 + ao + k0 * 2);
                ldsm4(a4, a5, a6, a7, aA1 + ao + k0 * 2);
                uint32_t b0, b1, b2, b3, b4, b5, b6, b7;
                ldsm4(b0, b1, b2, b3, bA0 + bo + k0 * 2);
                ldsm4(b4, b5, b6, b7, bA1 + bo + k0 * 2);
                mma16816(d[0][0], a0, a1, a2, a3, b0, b1);
                mma16816(d[0][1], a0, a1, a2, a3, b2, b3);
                mma16816(d[0][2], a0, a1, a2, a3, b4, b5);
                mma16816(d[0][3], a0, a1, a2, a3, b6, b7);
                mma16816(d[1][0], a4, a5, a6, a7, b0, b1);
                mma16816(d[1][1], a4, a5, a6, a7, b2, b3);
                mma16816(d[1][2], a4, a5, a6, a7, b4, b5);
                mma16816(d[1][3], a4, a5, a6, a7, b6, b7);
            }
        }

        // store C tile
        {
            const int g = lane >> 2, tig = lane & 3;
            float* Cb = C + (size_t)tile * 64 * 128;
            #pragma unroll
            for (int mb = 0; mb < 2; ++mb) {
                #pragma unroll
                for (int nb = 0; nb < 4; ++nb) {
                    int r = m0 + mb * 16 + g;
                    int c = n0 + nb * 8 + 2 * tig;
                    *(float2*)&Cb[r * 128 + c] =
                        make_float2(d[mb][nb][0], d[mb][nb][1]);
                    *(float2*)&Cb[(r + 8) * 128 + c] =
                        make_float2(d[mb][nb][2], d[mb][nb][3]);
                }
            }
        }

        __syncthreads();               // everyone done reading A images
        if (!have_next) break;

        // convert prefetched tile into A images
        #pragma unroll
        for (int it = 0; it < 8; ++it) {
            int f = tid + 256 * it;
            int row = f >> 5, c4 = (f & 31) << 2;
            uint32_t h0, l0, h1, l1;
            cvt_hi_lo2(v[it].x, v[it].y, h0, l0);
            cvt_hi_lo2(v[it].z, v[it].w, h1, l1);
            *(uint2*)&Ahi[row * WS + c4] = make_uint2(h0, h1);
            *(uint2*)&Alo[row * WS + c4] = make_uint2(l0, l1);
        }
        __syncthreads();
        tile = next;
    }
}

// ---------------------------------------------------------------------------
// GAT scatter layer: warp-per-batch. CTA = 8 warps = 8 batches.
// ---------------------------------------------------------------------------
#define GW 8

template <bool LAYER2>
__global__ __launch_bounds__(256) void gat_kernel(
    const float* __restrict__ Hpre,
    const int*   __restrict__ edges,
    const float* __restrict__ a_s,
    const float* __restrict__ a_d,
    const float* __restrict__ bias,
    float* __restrict__ out_h,
    float* __restrict__ out_pred,
    float* __restrict__ out_attn)
{
    __shared__ float    s_asn[GW][16], s_adn[GW][16], s_z[GW][16];
    __shared__ unsigned s_mk[GW][16];
    __shared__ float    s_Am[GW][200];
    __shared__ __align__(16) float s_At[GW][196];

    const int tid = threadIdx.x;
    const int w = tid >> 5, lane = tid & 31;
    const int b = blockIdx.x * GW + w;

    #pragma unroll
    for (int i = 0; i < 7; ++i) {
        int j = lane + 32 * i;
        if (j < 196) { s_Am[w][j] = 0.f; if (LAYER2) s_At[w][j] = 0.f; }
    }
    if (lane < 14) { s_mk[w][lane] = 0u; s_z[w][lane] = 0.f; }

    const float* hb = Hpre + (size_t)b * (Nn * Cd);
    float4 v[Nn];
    #pragma unroll
    for (int n = 0; n < Nn; ++n)
        v[n] = *(const float4*)&hb[n * Cd + lane * 4];
    const float4 as4 = *(const float4*)&a_s[lane * 4];
    const float4 ad4 = *(const float4*)&a_d[lane * 4];
    const float4 bi4 = *(const float4*)&bias[lane * 4];

    float pa[Nn], pd[Nn];
    #pragma unroll
    for (int n = 0; n < Nn; ++n) {
        pa[n] = v[n].x * as4.x + v[n].y * as4.y + v[n].z * as4.z + v[n].w * as4.w;
        pd[n] = v[n].x * ad4.x + v[n].y * ad4.y + v[n].z * ad4.z + v[n].w * ad4.w;
    }
    #pragma unroll
    for (int o = 16; o > 0; o >>= 1) {
        #pragma unroll
        for (int n = 0; n < Nn; ++n) {
            pa[n] += __shfl_xor_sync(0xffffffffu, pa[n], o);
            pd[n] += __shfl_xor_sync(0xffffffffu, pd[n], o);
        }
    }
    if (lane == 0) {
        #pragma unroll
        for (int n = 0; n < Nn; ++n) { s_asn[w][n] = pa[n]; s_adn[w][n] = pd[n]; }
    }
    __syncwarp();

    const int* eb = edges + (size_t)b * (Ed * 2);
    int  es_[3], ed_[3];
    float lg_[3], ev_[3];
    bool act[3];
    #pragma unroll
    for (int r = 0; r < 3; ++r) {
        int e = lane + 32 * r;
        act[r] = (e < 78);
        es_[r] = 0; ed_[r] = 0; lg_[r] = 0.f;
        if (act[r]) {
            int s, dd;
            if (e < Ed) { int2 p = *(const int2*)&eb[2 * e]; s = p.x; dd = p.y; }
            else        { s = dd = e - Ed; }
            float x = s_asn[w][s] + s_adn[w][dd];
            x = (x > 0.f) ? x : 0.2f * x;
            es_[r] = s; ed_[r] = dd; lg_[r] = x;
            atomicMax(&s_mk[w][dd], fkey(x));
        }
    }
    __syncwarp();
    #pragma unroll
    for (int r = 0; r < 3; ++r) {
        if (act[r]) {
            float m = kinv(s_mk[w][ed_[r]]);
            ev_[r] = expf(lg_[r] - m);
            atomicAdd(&s_z[w][ed_[r]], ev_[r]);
        }
    }
    __syncwarp();
    #pragma unroll
    for (int r = 0; r < 3; ++r) {
        if (act[r]) {
            float al = ev_[r] / s_z[w][ed_[r]];
            atomicAdd(&s_Am[w][ed_[r] * Nn + es_[r]], al);
            if (LAYER2) s_At[w][es_[r] * Nn + ed_[r]] = al;
        }
    }
    __syncwarp();

    if (!LAYER2) {
        float* ob = out_h + (size_t)b * (Nn * Cd);
        #pragma unroll
        for (int n = 0; n < Nn; ++n) {
            float4 acc = bi4;
            #pragma unroll
            for (int s = 0; s < Nn; ++s) {
                float am = s_Am[w][n * Nn + s];
                acc.x = fmaf(am, v[s].x, acc.x);
                acc.y = fmaf(am, v[s].y, acc.y);
                acc.z = fmaf(am, v[s].z, acc.z);
                acc.w = fmaf(am, v[s].w, acc.w);
            }
            acc.x = fmaxf(acc.x, 0.f); acc.y = fmaxf(acc.y, 0.f);
            acc.z = fmaxf(acc.z, 0.f); acc.w = fmaxf(acc.w, 0.f);
            *(float4*)&ob[n * Cd + lane * 4] = acc;
        }
    } else {
        float p = 0.f;
        #pragma unroll
        for (int n = 0; n < Nn; ++n) {
            float4 acc = bi4;
            #pragma unroll
            for (int s = 0; s < Nn; ++s) {
                float am = s_Am[w][n * Nn + s];
                acc.x = fmaf(am, v[s].x, acc.x);
                acc.y = fmaf(am, v[s].y, acc.y);
                acc.z = fmaf(am, v[s].z, acc.z);
                acc.w = fmaf(am, v[s].w, acc.w);
            }
            float4 wv = *(const float4*)&g_wlp.f[n * Cd + lane * 4];
            p += acc.x * wv.x + acc.y * wv.y + acc.z * wv.z + acc.w * wv.w;
        }
        #pragma unroll
        for (int o = 16; o > 0; o >>= 1)
            p += __shfl_xor_sync(0xffffffffu, p, o);
        if (lane == 0)
            out_pred[b] = 1.f / (1.f + expf(-(p + g_c0)));
        __syncwarp();
        float* ab = out_attn + (size_t)b * (Nn * Nn);
        #pragma unroll
        for (int i = 0; i < 2; ++i) {
            int j = lane + 32 * i;
            if (j < 49)
                *(float4*)&ab[4 * j] = *(const float4*)&s_At[w][4 * j];
        }
    }
}

// ---------------------------------------------------------------------------
extern "C" void kernel_launch(void* const* d_in, const int* in_sizes, int n_in,
                              void* d_out, int out_size)
{
    const float* feature = (const float*)d_in[0];
    const int*   edges   = (const int*)  d_in[1];
    const float* W1      = (const float*)d_in[2];
    const float* a_s1    = (const float*)d_in[3];
    const float* a_d1    = (const float*)d_in[4];
    const float* b1      = (const float*)d_in[5];
    const float* W2      = (const float*)d_in[6];
    const float* a_s2    = (const float*)d_in[7];
    const float* a_d2    = (const float*)d_in[8];
    const float* b2      = (const float*)d_in[9];
    const float* Wl      = (const float*)d_in[10];
    const float* bl      = (const float*)d_in[11];
    const float* Wp      = (const float*)d_in[12];
    const float* bp      = (const float*)d_in[13];

    float* out  = (float*)d_out;
    float* pred = out;            // [B]
    float* attn = out + Bn;       // [B,N,N]

    void *p_buf0, *p_h1, *p_w1h, *p_w1l, *p_w2h, *p_w2l;
    cudaGetSymbolAddress(&p_buf0, g_buf0);
    cudaGetSymbolAddress(&p_h1,   g_h1);
    cudaGetSymbolAddress(&p_w1h,  g_w1hi);
    cudaGetSymbolAddress(&p_w1l,  g_w1lo);
    cudaGetSymbolAddress(&p_w2h,  g_w2hi);
    cudaGetSymbolAddress(&p_w2l,  g_w2lo);
    float* buf0 = (float*)p_buf0;
    float* h1   = (float*)p_h1;
    __nv_bfloat16* w1h = (__nv_bfloat16*)p_w1h;
    __nv_bfloat16* w1l = (__nv_bfloat16*)p_w1l;
    __nv_bfloat16* w2h = (__nv_bfloat16*)p_w2h;
    __nv_bfloat16* w2l = (__nv_bfloat16*)p_w2l;

    cudaFuncSetAttribute(tgemm_kernel,
                         cudaFuncAttributeMaxDynamicSharedMemorySize, TG_SMEM);

    // 0. pre-convert weights into padded bf16 hi/lo images
    prep_w_kernel<<<128, 128>>>(W1, w1h, w1l);
    prep_w_kernel<<<128, 128>>>(W2, w2h, w2l);

    // 1. collapse prediction head
    wlp_kernel<<<14, 128>>>(Wl, Wp, bl, bp);

    // 2. Hpre1 = feature @ W1  (persistent HMMA split-bf16)
    tgemm_kernel<<<GRID_G, 256, TG_SMEM>>>(feature, w1h, w1l, buf0);

    // 3. GAT layer 1 (relu epilogue)
    gat_kernel<false><<<Bn / GW, 256>>>(buf0, edges, a_s1, a_d1, b1, h1, nullptr, nullptr);

    // 4. Hpre2 = h1 @ W2
    tgemm_kernel<<<GRID_G, 256, TG_SMEM>>>(h1, w2h, w2l, buf0);

    // 5. GAT layer 2 + attn + fused sigmoid head
    gat_kernel<true><<<Bn / GW, 256>>>(buf0, edges, a_s2, a_d2, b2, nullptr, pred, attn);
}

// round 9
// speedup vs baseline: 1.6745x; 1.5620x over previous
#include <cuda_runtime.h>
#include <cuda_bf16.h>
#include <cstdint>
#include <math.h>

// Problem constants
#define Bn   32768
#define Nn   14
#define Ed   64
#define Cd   128
#define Mrows (Bn * 14)    // 458752 = 3584 * 128
#define NT128 3584         // 128-row M-tiles
#define GRID_P 148         // persistent: 1 CTA per SM

#define WS   136           // padded bf16 row stride (272B; conflict-free ldsm)
#define IMG  34816         // one 128x128 bf16 image in smem (128*WS*2)

// ---------------------------------------------------------------------------
// Scratch
// ---------------------------------------------------------------------------
struct __align__(16) FBuf  { float f[(size_t)Mrows * Cd]; };
struct __align__(16) HBuf  { __nv_bfloat16 h[(size_t)Mrows * Cd]; };
struct __align__(16) WBuf  { __nv_bfloat16 h[128 * WS]; };
struct __align__(16) WlpBuf{ float f[Nn * Cd]; };

__device__ FBuf   g_buf0;                      // Hpre1 / Hpre2 (fp32)
__device__ HBuf   g_a2hi, g_a2lo;              // h1 pre-split bf16 images
__device__ WlpBuf g_wlp;
__device__ float  g_c0;
__device__ WBuf   g_w1hi, g_w1lo, g_w2hi, g_w2lo;

// ---------------------------------------------------------------------------
// Helpers
// ---------------------------------------------------------------------------
__device__ __forceinline__ void cvt_hi_lo(float f, __nv_bfloat16& hi, __nv_bfloat16& lo)
{
    hi = __float2bfloat16(f);
    lo = __float2bfloat16(f - __bfloat162float(hi));
}
__device__ __forceinline__ void cvt_hi_lo2(float f0, float f1, uint32_t& hi, uint32_t& lo)
{
    __nv_bfloat16 h0, l0, h1, l1;
    cvt_hi_lo(f0, h0, l0);
    cvt_hi_lo(f1, h1, l1);
    __nv_bfloat162 hp = __halves2bfloat162(h0, h1);
    __nv_bfloat162 lp = __halves2bfloat162(l0, l1);
    hi = *reinterpret_cast<uint32_t*>(&hp);
    lo = *reinterpret_cast<uint32_t*>(&lp);
}

__device__ __forceinline__ unsigned fkey(float x)
{
    unsigned u = __float_as_uint(x);
    return u ^ ((unsigned)(((int)u) >> 31) | 0x80000000u);
}
__device__ __forceinline__ float kinv(unsigned k)
{
    unsigned u = k ^ ((k & 0x80000000u) ? 0x80000000u : 0xFFFFFFFFu);
    return __uint_as_float(u);
}

__device__ __forceinline__ uint32_t smem_u32(const void* p)
{
    uint32_t a;
    asm("{ .reg .u64 t; cvta.to.shared.u64 t, %1; cvt.u32.u64 %0, t; }"
        : "=r"(a) : "l"(p));
    return a;
}
__device__ __forceinline__ void cp16(uint32_t dst, const void* src)
{
    asm volatile("cp.async.cg.shared.global [%0], [%1], 16;"
                 :: "r"(dst), "l"(src));
}
__device__ __forceinline__ void ldsm4(uint32_t* r, uint32_t addr)
{
    asm volatile("ldmatrix.sync.aligned.m8n8.x4.shared.b16 {%0,%1,%2,%3}, [%4];"
                 : "=r"(r[0]), "=r"(r[1]), "=r"(r[2]), "=r"(r[3]) : "r"(addr));
}

// m16n8k16 bf16 MMA (base-target HMMA)
__device__ __forceinline__ void mma16816(float* d, const uint32_t* a,
                                         uint32_t b0, uint32_t b1)
{
    asm volatile(
        "mma.sync.aligned.m16n8k16.row.col.f32.bf16.bf16.f32 "
        "{%0,%1,%2,%3}, {%4,%5,%6,%7}, {%8,%9}, {%0,%1,%2,%3};"
        : "+f"(d[0]), "+f"(d[1]), "+f"(d[2]), "+f"(d[3])
        : "r"(a[0]), "r"(a[1]), "r"(a[2]), "r"(a[3]), "r"(b0), "r"(b1));
}

// ---------------------------------------------------------------------------
// Weight prep: W[k,n] fp32 -> hi/lo bf16 images [n][k] WS-padded
// ---------------------------------------------------------------------------
__global__ void prep_w_kernel(const float* __restrict__ W,
                              __nv_bfloat16* __restrict__ ohi,
                              __nv_bfloat16* __restrict__ olo)
{
    int idx = blockIdx.x * blockDim.x + threadIdx.x;
    if (idx >= 128 * 128) return;
    int n = idx >> 7, k = idx & 127;
    float w = W[k * 128 + n];
    __nv_bfloat16 hi, lo;
    cvt_hi_lo(w, hi, lo);
    ohi[n * WS + k] = hi;
    olo[n * WS + k] = lo;
}

__global__ void wlp_kernel(const float* __restrict__ Wl,
                           const float* __restrict__ Wp,
                           const float* __restrict__ bl,
                           const float* __restrict__ bp)
{
    int idx = blockIdx.x * blockDim.x + threadIdx.x;
    if (idx < Nn * Cd) {
        const float* row = Wl + (size_t)idx * 64;
        float s = 0.f;
        #pragma unroll
        for (int j = 0; j < 64; ++j) s = fmaf(row[j], Wp[j], s);
        g_wlp.f[idx] = s;
    }
    if (idx == 0) {
        float s = bp[0];
        #pragma unroll
        for (int j = 0; j < 64; ++j) s = fmaf(bl[j], Wp[j], s);
        g_c0 = s;
    }
}

// ---------------------------------------------------------------------------
// Shared GEMM core pieces
// smem layout: A buf0 hi | buf0 lo | buf1 hi | buf1 lo | B hi | B lo  (6*IMG)
// Warp tile 64x32 (warp grid 2m x 4n on a 128x128 CTA tile), 8 warps.
// Fused 3-pass per k-step: 12 ldsm.x4 -> 48 MMA.
// ---------------------------------------------------------------------------
#define TG_SMEM (6 * IMG)   // 208896

struct MmaCtx {
    uint32_t aoff;       // lane offset within an A image
    uint32_t bA0, bA1;   // B hi-image lane addresses (n0, n0+16)
    int m0, n0, g, tig;
};

__device__ __forceinline__ MmaCtx make_ctx(uint32_t sb, int tid)
{
    MmaCtx c;
    const int w = tid >> 5, lane = tid & 31;
    const int blk = lane >> 3, rw = lane & 7;
    c.m0 = (w >> 2) * 64;
    c.n0 = (w & 3) * 32;
    c.g = lane >> 2; c.tig = lane & 3;
    c.aoff = (uint32_t)(((c.m0 + rw + (blk & 1) * 8) * WS + (blk >> 1) * 8) * 2);
    const uint32_t sB = sb + 4 * IMG;
    c.bA0 = sB + ((c.n0 + rw + (blk >> 1) * 8) * WS + (blk & 1) * 8) * 2;
    c.bA1 = c.bA0 + 16 * WS * 2;
    return c;
}

// MMA over one A buffer; writes C tile
__device__ __forceinline__ void do_tile_mma(const MmaCtx& c, uint32_t abase,
                                            float* __restrict__ Cb)
{
    float d[4][4][4];
    #pragma unroll
    for (int mb = 0; mb < 4; ++mb)
        #pragma unroll
        for (int nb = 0; nb < 4; ++nb)
            #pragma unroll
            for (int j = 0; j < 4; ++j) d[mb][nb][j] = 0.f;

    #pragma unroll
    for (int k0 = 0; k0 < 128; k0 += 16) {
        uint32_t ah[4][4], al[4][4], bh[2][4], bl[2][4];
        #pragma unroll
        for (int mb = 0; mb < 4; ++mb) {
            uint32_t ad = abase + c.aoff + (uint32_t)(mb * 16 * WS * 2 + k0 * 2);
            ldsm4(ah[mb], ad);
            ldsm4(al[mb], ad + IMG);
        }
        ldsm4(bh[0], c.bA0 + k0 * 2);
        ldsm4(bh[1], c.bA1 + k0 * 2);
        ldsm4(bl[0], c.bA0 + IMG + k0 * 2);
        ldsm4(bl[1], c.bA1 + IMG + k0 * 2);

        // pass HH
        #pragma unroll
        for (int mb = 0; mb < 4; ++mb)
            #pragma unroll
            for (int nb = 0; nb < 2; ++nb) {
                mma16816(d[mb][2 * nb],     ah[mb], bh[nb][0], bh[nb][1]);
                mma16816(d[mb][2 * nb + 1], ah[mb], bh[nb][2], bh[nb][3]);
            }
        // pass HL
        #pragma unroll
        for (int mb = 0; mb < 4; ++mb)
            #pragma unroll
            for (int nb = 0; nb < 2; ++nb) {
                mma16816(d[mb][2 * nb],     ah[mb], bl[nb][0], bl[nb][1]);
                mma16816(d[mb][2 * nb + 1], ah[mb], bl[nb][2], bl[nb][3]);
            }
        // pass LH
        #pragma unroll
        for (int mb = 0; mb < 4; ++mb)
            #pragma unroll
            for (int nb = 0; nb < 2; ++nb) {
                mma16816(d[mb][2 * nb],     al[mb], bh[nb][0], bh[nb][1]);
                mma16816(d[mb][2 * nb + 1], al[mb], bh[nb][2], bh[nb][3]);
            }
    }

    #pragma unroll
    for (int mb = 0; mb < 4; ++mb)
        #pragma unroll
        for (int nb = 0; nb < 4; ++nb) {
            int r = c.m0 + mb * 16 + c.g;
            int col = c.n0 + nb * 8 + 2 * c.tig;
            *(float2*)&Cb[r * 128 + col] =
                make_float2(d[mb][nb][0], d[mb][nb][1]);
            *(float2*)&Cb[(r + 8) * 128 + col] =
                make_float2(d[mb][nb][2], d[mb][nb][3]);
        }
}

// ---------------------------------------------------------------------------
// tgemm variant 1: A is fp32, converted in-kernel (double-buffered images)
// ---------------------------------------------------------------------------
__global__ __launch_bounds__(256, 1) void tgemm_cvt(
    const float* __restrict__ A,
    const __nv_bfloat16* __restrict__ whi,
    const __nv_bfloat16* __restrict__ wlo,
    float* __restrict__ C)
{
    extern __shared__ __align__(16) uint8_t smem[];
    const int tid = threadIdx.x;
    const uint32_t sb = smem_u32(smem);
    __nv_bfloat16* Abuf = (__nv_bfloat16*)smem;   // element view

    // B images via cp.async
    {
        const uint4* s1 = (const uint4*)whi;
        const uint4* s2 = (const uint4*)wlo;
        #pragma unroll
        for (int i = 0; i < 9; ++i) {
            int j = tid + 256 * i;
            if (j < 2176) {
                cp16(sb + 4 * IMG + 16 * j, s1 + j);
                cp16(sb + 5 * IMG + 16 * j, s2 + j);
            }
        }
        asm volatile("cp.async.commit_group;");
    }

    float4 v[16];
    int tile = blockIdx.x;
    // tile0: load + convert into buf0
    {
        const float* Ab = A + (size_t)tile * 16384;
        #pragma unroll
        for (int it = 0; it < 16; ++it) {
            int f = tid + 256 * it;
            v[it] = *(const float4*)&Ab[(f >> 5) * 128 + ((f & 31) << 2)];
        }
        #pragma unroll
        for (int it = 0; it < 16; ++it) {
            int f = tid + 256 * it;
            int row = f >> 5, c4 = (f & 31) << 2;
            uint32_t h0, l0, h1, l1;
            cvt_hi_lo2(v[it].x, v[it].y, h0, l0);
            cvt_hi_lo2(v[it].z, v[it].w, h1, l1);
            *(uint2*)&Abuf[row * WS + c4] = make_uint2(h0, h1);
            *(uint2*)&Abuf[IMG / 2 + row * WS + c4] = make_uint2(l0, l1);
        }
    }
    asm volatile("cp.async.wait_group 0;");
    __syncthreads();

    const MmaCtx ctx = make_ctx(sb, tid);
    int par = 0;

    while (true) {
        const int next = tile + GRID_P;
        const bool have = (next < NT128);

        if (have) {
            const float* Ab = A + (size_t)next * 16384;
            #pragma unroll
            for (int it = 0; it < 16; ++it) {
                int f = tid + 256 * it;
                v[it] = *(const float4*)&Ab[(f >> 5) * 128 + ((f & 31) << 2)];
            }
        }

        do_tile_mma(ctx, sb + (uint32_t)(par * 2 * IMG), C + (size_t)tile * 16384);

        if (!have) break;

        // convert prefetched tile into the other buffer
        __nv_bfloat16* dst = Abuf + (par ^ 1) * (IMG);   // (IMG bytes*2)/2 elems
        #pragma unroll
        for (int it = 0; it < 16; ++it) {
            int f = tid + 256 * it;
            int row = f >> 5, c4 = (f & 31) << 2;
            uint32_t h0, l0, h1, l1;
            cvt_hi_lo2(v[it].x, v[it].y, h0, l0);
            cvt_hi_lo2(v[it].z, v[it].w, h1, l1);
            *(uint2*)&dst[row * WS + c4] = make_uint2(h0, h1);
            *(uint2*)&dst[IMG / 2 + row * WS + c4] = make_uint2(l0, l1);
        }
        __syncthreads();
        par ^= 1;
        tile = next;
    }
}

// ---------------------------------------------------------------------------
// tgemm variant 2: A pre-split bf16 hi/lo images in gmem ([row][128] packed)
// ---------------------------------------------------------------------------
__global__ __launch_bounds__(256, 1) void tgemm_pre(
    const __nv_bfloat16* __restrict__ Ahi,
    const __nv_bfloat16* __restrict__ Alo,
    const __nv_bfloat16* __restrict__ whi,
    const __nv_bfloat16* __restrict__ wlo,
    float* __restrict__ C)
{
    extern __shared__ __align__(16) uint8_t smem[];
    const int tid = threadIdx.x;
    const uint32_t sb = smem_u32(smem);

    // B images + A tile0 via cp.async
    {
        const uint4* s1 = (const uint4*)whi;
        const uint4* s2 = (const uint4*)wlo;
        #pragma unroll
        for (int i = 0; i < 9; ++i) {
            int j = tid + 256 * i;
            if (j < 2176) {
                cp16(sb + 4 * IMG + 16 * j, s1 + j);
                cp16(sb + 5 * IMG + 16 * j, s2 + j);
            }
        }
    }
    int tile = blockIdx.x;
    {
        const char* sh = (const char*)Ahi + (size_t)tile * 16384 * 2;
        const char* sl = (const char*)Alo + (size_t)tile * 16384 * 2;
        #pragma unroll
        for (int i = 0; i < 8; ++i) {
            int j = tid + 256 * i;            // granule 0..2047
            int row = j >> 4, gg = j & 15;
            uint32_t doff = (uint32_t)(row * WS * 2 + gg * 16);
            cp16(sb + doff, sh + row * 256 + gg * 16);
            cp16(sb + IMG + doff, sl + row * 256 + gg * 16);
        }
        asm volatile("cp.async.commit_group;");
    }
    asm volatile("cp.async.wait_group 0;");
    __syncthreads();

    const MmaCtx ctx = make_ctx(sb, tid);
    int par = 0;

    while (true) {
        const int next = tile + GRID_P;
        const bool have = (next < NT128);

        if (have) {
            const uint32_t base = sb + (uint32_t)((par ^ 1) * 2 * IMG);
            const char* sh = (const char*)Ahi + (size_t)next * 16384 * 2;
            const char* sl = (const char*)Alo + (size_t)next * 16384 * 2;
            #pragma unroll
            for (int i = 0; i < 8; ++i) {
                int j = tid + 256 * i;
                int row = j >> 4, gg = j & 15;
                uint32_t doff = (uint32_t)(row * WS * 2 + gg * 16);
                cp16(base + doff, sh + row * 256 + gg * 16);
                cp16(base + IMG + doff, sl + row * 256 + gg * 16);
            }
            asm volatile("cp.async.commit_group;");
        }

        do_tile_mma(ctx, sb + (uint32_t)(par * 2 * IMG), C + (size_t)tile * 16384);

        if (!have) break;
        asm volatile("cp.async.wait_group 0;");
        __syncthreads();
        par ^= 1;
        tile = next;
    }
}

// ---------------------------------------------------------------------------
// GAT scatter layer: warp-per-batch. CTA = 8 warps = 8 batches.
// Layer1 writes h1 as pre-split bf16 hi/lo images (relu first).
// ---------------------------------------------------------------------------
#define GW 8

template <bool LAYER2>
__global__ __launch_bounds__(256) void gat_kernel(
    const float* __restrict__ Hpre,
    const int*   __restrict__ edges,
    const float* __restrict__ a_s,
    const float* __restrict__ a_d,
    const float* __restrict__ bias,
    __nv_bfloat16* __restrict__ out_hi,
    __nv_bfloat16* __restrict__ out_lo,
    float* __restrict__ out_pred,
    float* __restrict__ out_attn)
{
    __shared__ float    s_asn[GW][16], s_adn[GW][16], s_z[GW][16];
    __shared__ unsigned s_mk[GW][16];
    __shared__ float    s_Am[GW][200];
    __shared__ __align__(16) float s_At[GW][196];

    const int tid = threadIdx.x;
    const int w = tid >> 5, lane = tid & 31;
    const int b = blockIdx.x * GW + w;

    #pragma unroll
    for (int i = 0; i < 7; ++i) {
        int j = lane + 32 * i;
        if (j < 196) { s_Am[w][j] = 0.f; if (LAYER2) s_At[w][j] = 0.f; }
    }
    if (lane < 14) { s_mk[w][lane] = 0u; s_z[w][lane] = 0.f; }

    const float* hb = Hpre + (size_t)b * (Nn * Cd);
    float4 v[Nn];
    #pragma unroll
    for (int n = 0; n < Nn; ++n)
        v[n] = *(const float4*)&hb[n * Cd + lane * 4];
    const float4 as4 = *(const float4*)&a_s[lane * 4];
    const float4 ad4 = *(const float4*)&a_d[lane * 4];
    const float4 bi4 = *(const float4*)&bias[lane * 4];

    float pa[Nn], pd[Nn];
    #pragma unroll
    for (int n = 0; n < Nn; ++n) {
        pa[n] = v[n].x * as4.x + v[n].y * as4.y + v[n].z * as4.z + v[n].w * as4.w;
        pd[n] = v[n].x * ad4.x + v[n].y * ad4.y + v[n].z * ad4.z + v[n].w * ad4.w;
    }
    #pragma unroll
    for (int o = 16; o > 0; o >>= 1) {
        #pragma unroll
        for (int n = 0; n < Nn; ++n) {
            pa[n] += __shfl_xor_sync(0xffffffffu, pa[n], o);
            pd[n] += __shfl_xor_sync(0xffffffffu, pd[n], o);
        }
    }
    if (lane == 0) {
        #pragma unroll
        for (int n = 0; n < Nn; ++n) { s_asn[w][n] = pa[n]; s_adn[w][n] = pd[n]; }
    }
    __syncwarp();

    const int* eb = edges + (size_t)b * (Ed * 2);
    int  es_[3], ed_[3];
    float lg_[3], ev_[3];
    bool act[3];
    #pragma unroll
    for (int r = 0; r < 3; ++r) {
        int e = lane + 32 * r;
        act[r] = (e < 78);
        es_[r] = 0; ed_[r] = 0; lg_[r] = 0.f;
        if (act[r]) {
            int s, dd;
            if (e < Ed) { int2 p = *(const int2*)&eb[2 * e]; s = p.x; dd = p.y; }
            else        { s = dd = e - Ed; }
            float x = s_asn[w][s] + s_adn[w][dd];
            x = (x > 0.f) ? x : 0.2f * x;
            es_[r] = s; ed_[r] = dd; lg_[r] = x;
            atomicMax(&s_mk[w][dd], fkey(x));
        }
    }
    __syncwarp();
    #pragma unroll
    for (int r = 0; r < 3; ++r) {
        if (act[r]) {
            float m = kinv(s_mk[w][ed_[r]]);
            ev_[r] = expf(lg_[r] - m);
            atomicAdd(&s_z[w][ed_[r]], ev_[r]);
        }
    }
    __syncwarp();
    #pragma unroll
    for (int r = 0; r < 3; ++r) {
        if (act[r]) {
            float al = ev_[r] / s_z[w][ed_[r]];
            atomicAdd(&s_Am[w][ed_[r] * Nn + es_[r]], al);
            if (LAYER2) s_At[w][es_[r] * Nn + ed_[r]] = al;
        }
    }
    __syncwarp();

    if (!LAYER2) {
        #pragma unroll
        for (int n = 0; n < Nn; ++n) {
            float4 acc = bi4;
            #pragma unroll
            for (int s = 0; s < Nn; ++s) {
                float am = s_Am[w][n * Nn + s];
                acc.x = fmaf(am, v[s].x, acc.x);
                acc.y = fmaf(am, v[s].y, acc.y);
                acc.z = fmaf(am, v[s].z, acc.z);
                acc.w = fmaf(am, v[s].w, acc.w);
            }
            acc.x = fmaxf(acc.x, 0.f); acc.y = fmaxf(acc.y, 0.f);
            acc.z = fmaxf(acc.z, 0.f); acc.w = fmaxf(acc.w, 0.f);
            // write pre-split bf16 hi/lo
            uint32_t h0, l0, h1, l1;
            cvt_hi_lo2(acc.x, acc.y, h0, l0);
            cvt_hi_lo2(acc.z, acc.w, h1, l1);
            size_t off = (size_t)(b * Nn + n) * 128 + lane * 4;
            *(uint2*)&out_hi[off] = make_uint2(h0, h1);
            *(uint2*)&out_lo[off] = make_uint2(l0, l1);
        }
    } else {
        float p = 0.f;
        #pragma unroll
        for (int n = 0; n < Nn; ++n) {
            float4 acc = bi4;
            #pragma unroll
            for (int s = 0; s < Nn; ++s) {
                float am = s_Am[w][n * Nn + s];
                acc.x = fmaf(am, v[s].x, acc.x);
                acc.y = fmaf(am, v[s].y, acc.y);
                acc.z = fmaf(am, v[s].z, acc.z);
                acc.w = fmaf(am, v[s].w, acc.w);
            }
            float4 wv = *(const float4*)&g_wlp.f[n * Cd + lane * 4];
            p += acc.x * wv.x + acc.y * wv.y + acc.z * wv.z + acc.w * wv.w;
        }
        #pragma unroll
        for (int o = 16; o > 0; o >>= 1)
            p += __shfl_xor_sync(0xffffffffu, p, o);
        if (lane == 0)
            out_pred[b] = 1.f / (1.f + expf(-(p + g_c0)));
        __syncwarp();
        float* ab = out_attn + (size_t)b * (Nn * Nn);
        #pragma unroll
        for (int i = 0; i < 2; ++i) {
            int j = lane + 32 * i;
            if (j < 49)
                *(float4*)&ab[4 * j] = *(const float4*)&s_At[w][4 * j];
        }
    }
}

// ---------------------------------------------------------------------------
extern "C" void kernel_launch(void* const* d_in, const int* in_sizes, int n_in,
                              void* d_out, int out_size)
{
    const float* feature = (const float*)d_in[0];
    const int*   edges   = (const int*)  d_in[1];
    const float* W1      = (const float*)d_in[2];
    const float* a_s1    = (const float*)d_in[3];
    const float* a_d1    = (const float*)d_in[4];
    const float* b1      = (const float*)d_in[5];
    const float* W2      = (const float*)d_in[6];
    const float* a_s2    = (const float*)d_in[7];
    const float* a_d2    = (const float*)d_in[8];
    const float* b2      = (const float*)d_in[9];
    const float* Wl      = (const float*)d_in[10];
    const float* bl      = (const float*)d_in[11];
    const float* Wp      = (const float*)d_in[12];
    const float* bp      = (const float*)d_in[13];

    float* out  = (float*)d_out;
    float* pred = out;            // [B]
    float* attn = out + Bn;       // [B,N,N]

    void *p_buf0, *p_a2h, *p_a2l, *p_w1h, *p_w1l, *p_w2h, *p_w2l;
    cudaGetSymbolAddress(&p_buf0, g_buf0);
    cudaGetSymbolAddress(&p_a2h,  g_a2hi);
    cudaGetSymbolAddress(&p_a2l,  g_a2lo);
    cudaGetSymbolAddress(&p_w1h,  g_w1hi);
    cudaGetSymbolAddress(&p_w1l,  g_w1lo);
    cudaGetSymbolAddress(&p_w2h,  g_w2hi);
    cudaGetSymbolAddress(&p_w2l,  g_w2lo);
    float* buf0 = (float*)p_buf0;
    __nv_bfloat16* a2h = (__nv_bfloat16*)p_a2h;
    __nv_bfloat16* a2l = (__nv_bfloat16*)p_a2l;
    __nv_bfloat16* w1h = (__nv_bfloat16*)p_w1h;
    __nv_bfloat16* w1l = (__nv_bfloat16*)p_w1l;
    __nv_bfloat16* w2h = (__nv_bfloat16*)p_w2h;
    __nv_bfloat16* w2l = (__nv_bfloat16*)p_w2l;

    cudaFuncSetAttribute(tgemm_cvt,
                         cudaFuncAttributeMaxDynamicSharedMemorySize, TG_SMEM);
    cudaFuncSetAttribute(tgemm_pre,
                         cudaFuncAttributeMaxDynamicSharedMemorySize, TG_SMEM);

    // 0. pre-convert weights
    prep_w_kernel<<<128, 128>>>(W1, w1h, w1l);
    prep_w_kernel<<<128, 128>>>(W2, w2h, w2l);

    // 1. collapse prediction head
    wlp_kernel<<<14, 128>>>(Wl, Wp, bl, bp);

    // 2. Hpre1 = feature @ W1  (persistent, in-kernel convert)
    tgemm_cvt<<<GRID_P, 256, TG_SMEM>>>(feature, w1h, w1l, buf0);

    // 3. GAT layer 1 -> h1 as pre-split bf16 images
    gat_kernel<false><<<Bn / GW, 256>>>(buf0, edges, a_s1, a_d1, b1,
                                        a2h, a2l, nullptr, nullptr);

    // 4. Hpre2 = h1 @ W2  (persistent, pure cp.async A)
    tgemm_pre<<<GRID_P, 256, TG_SMEM>>>(a2h, a2l, w2h, w2l, buf0);

    // 5. GAT layer 2 + attn + fused sigmoid head
    gat_kernel<true><<<Bn / GW, 256>>>(buf0, edges, a_s2, a_d2, b2,
                                       nullptr, nullptr, pred, attn);
}

// round 11
// speedup vs baseline: 1.8140x; 1.0833x over previous
#include <cuda_runtime.h>
#include <cuda_bf16.h>
#include <cstdint>
#include <math.h>

// Problem constants
#define Bn   32768
#define Nn   14
#define Ed   64
#define Cd   128
#define Mrows (Bn * 14)    // 458752 = 3584 * 128
#define NT128 3584         // 128-row M-tiles
#define GRID_P 148         // persistent: 1 CTA per SM

#define WS   136           // padded bf16 row stride (272B; conflict-free ldsm)
#define IMG  34816         // one 128x128 bf16 image in smem (128*WS*2)

#define NTHREADS 384       // 8 consumer warps + 4 producer warps

// ---------------------------------------------------------------------------
// Scratch
// ---------------------------------------------------------------------------
struct __align__(16) FBuf  { float f[(size_t)Mrows * Cd]; };
struct __align__(16) HBuf  { __nv_bfloat16 h[(size_t)Mrows * Cd]; };
struct __align__(16) WBuf  { __nv_bfloat16 h[128 * WS]; };
struct __align__(16) WlpBuf{ float f[Nn * Cd]; };

__device__ FBuf   g_buf0;                      // Hpre1 / Hpre2 (fp32)
__device__ HBuf   g_a2hi, g_a2lo;              // h1 pre-split bf16 images
__device__ WlpBuf g_wlp;
__device__ float  g_c0;
__device__ WBuf   g_w1hi, g_w1lo, g_w2hi, g_w2lo;

// ---------------------------------------------------------------------------
// Helpers
// ---------------------------------------------------------------------------
__device__ __forceinline__ void cvt_hi_lo(float f, __nv_bfloat16& hi, __nv_bfloat16& lo)
{
    hi = __float2bfloat16(f);
    lo = __float2bfloat16(f - __bfloat162float(hi));
}
__device__ __forceinline__ void cvt_hi_lo2(float f0, float f1, uint32_t& hi, uint32_t& lo)
{
    __nv_bfloat16 h0, l0, h1, l1;
    cvt_hi_lo(f0, h0, l0);
    cvt_hi_lo(f1, h1, l1);
    __nv_bfloat162 hp = __halves2bfloat162(h0, h1);
    __nv_bfloat162 lp = __halves2bfloat162(l0, l1);
    hi = *reinterpret_cast<uint32_t*>(&hp);
    lo = *reinterpret_cast<uint32_t*>(&lp);
}

__device__ __forceinline__ unsigned fkey(float x)
{
    unsigned u = __float_as_uint(x);
    return u ^ ((unsigned)(((int)u) >> 31) | 0x80000000u);
}
__device__ __forceinline__ float kinv(unsigned k)
{
    unsigned u = k ^ ((k & 0x80000000u) ? 0x80000000u : 0xFFFFFFFFu);
    return __uint_as_float(u);
}

__device__ __forceinline__ uint32_t smem_u32(const void* p)
{
    uint32_t a;
    asm("{ .reg .u64 t; cvta.to.shared.u64 t, %1; cvt.u32.u64 %0, t; }"
        : "=r"(a) : "l"(p));
    return a;
}
__device__ __forceinline__ void cp16(uint32_t dst, const void* src)
{
    asm volatile("cp.async.cg.shared.global [%0], [%1], 16;"
                 :: "r"(dst), "l"(src));
}
__device__ __forceinline__ void ldsm4(uint32_t* r, uint32_t addr)
{
    asm volatile("ldmatrix.sync.aligned.m8n8.x4.shared.b16 {%0,%1,%2,%3}, [%4];"
                 : "=r"(r[0]), "=r"(r[1]), "=r"(r[2]), "=r"(r[3]) : "r"(addr));
}

// m16n8k16 bf16 MMA (base-target HMMA)
__device__ __forceinline__ void mma16816(float* d, const uint32_t* a,
                                         uint32_t b0, uint32_t b1)
{
    asm volatile(
        "mma.sync.aligned.m16n8k16.row.col.f32.bf16.bf16.f32 "
        "{%0,%1,%2,%3}, {%4,%5,%6,%7}, {%8,%9}, {%0,%1,%2,%3};"
        : "+f"(d[0]), "+f"(d[1]), "+f"(d[2]), "+f"(d[3])
        : "r"(a[0]), "r"(a[1]), "r"(a[2]), "r"(a[3]), "r"(b0), "r"(b1));
}

// ---------------------------------------------------------------------------
// Weight prep + head collapse
// ---------------------------------------------------------------------------
__global__ void prep_w_kernel(const float* __restrict__ W,
                              __nv_bfloat16* __restrict__ ohi,
                              __nv_bfloat16* __restrict__ olo)
{
    int idx = blockIdx.x * blockDim.x + threadIdx.x;
    if (idx >= 128 * 128) return;
    int n = idx >> 7, k = idx & 127;
    float w = W[k * 128 + n];
    __nv_bfloat16 hi, lo;
    cvt_hi_lo(w, hi, lo);
    ohi[n * WS + k] = hi;
    olo[n * WS + k] = lo;
}

__global__ void wlp_kernel(const float* __restrict__ Wl,
                           const float* __restrict__ Wp,
                           const float* __restrict__ bl,
                           const float* __restrict__ bp)
{
    int idx = blockIdx.x * blockDim.x + threadIdx.x;
    if (idx < Nn * Cd) {
        const float* row = Wl + (size_t)idx * 64;
        float s = 0.f;
        #pragma unroll
        for (int j = 0; j < 64; ++j) s = fmaf(row[j], Wp[j], s);
        g_wlp.f[idx] = s;
    }
    if (idx == 0) {
        float s = bp[0];
        #pragma unroll
        for (int j = 0; j < 64; ++j) s = fmaf(bl[j], Wp[j], s);
        g_c0 = s;
    }
}

// ---------------------------------------------------------------------------
// GEMM core. smem: Abuf0 hi|lo, Abuf1 hi|lo, Bhi, Blo = 6*IMG.
// Consumers: warps 0-7, warp tile 64x32 (2m x 4n), 128x128 CTA tile.
// Producers: warps 8-11, fill the other A buffer for tile+GRID_P.
// ---------------------------------------------------------------------------
#define TG_SMEM (6 * IMG)   // 208896

struct MmaCtx {
    uint32_t aoff;
    uint32_t bA0, bA1;
    int m0, n0, g, tig;
};

__device__ __forceinline__ MmaCtx make_ctx(uint32_t sb, int tid)
{
    MmaCtx c;
    const int w = tid >> 5, lane = tid & 31;
    const int blk = lane >> 3, rw = lane & 7;
    c.m0 = (w >> 2) * 64;
    c.n0 = (w & 3) * 32;
    c.g = lane >> 2; c.tig = lane & 3;
    c.aoff = (uint32_t)(((c.m0 + rw + (blk & 1) * 8) * WS + (blk >> 1) * 8) * 2);
    const uint32_t sB = sb + 4 * IMG;
    c.bA0 = sB + ((c.n0 + rw + (blk >> 1) * 8) * WS + (blk & 1) * 8) * 2;
    c.bA1 = c.bA0 + 16 * WS * 2;
    return c;
}

// Consumer: MMA over one A buffer, store C tile.
__device__ __forceinline__ void do_tile_mma(const MmaCtx& c, uint32_t abase,
                                            float* __restrict__ Cb)
{
    float d[4][4][4];
    #pragma unroll
    for (int mb = 0; mb < 4; ++mb)
        #pragma unroll
        for (int nb = 0; nb < 4; ++nb)
            #pragma unroll
            for (int j = 0; j < 4; ++j) d[mb][nb][j] = 0.f;

    #pragma unroll
    for (int k0 = 0; k0 < 128; k0 += 16) {
        uint32_t bh[2][4], bl[2][4];
        ldsm4(bh[0], c.bA0 + k0 * 2);
        ldsm4(bh[1], c.bA1 + k0 * 2);
        ldsm4(bl[0], c.bA0 + IMG + k0 * 2);
        ldsm4(bl[1], c.bA1 + IMG + k0 * 2);

        #pragma unroll
        for (int mb = 0; mb < 4; ++mb) {
            uint32_t ah[4], al[4];
            uint32_t ad = abase + c.aoff + (uint32_t)(mb * 16 * WS * 2 + k0 * 2);
            ldsm4(ah, ad);
            ldsm4(al, ad + IMG);
            // HH
            mma16816(d[mb][0], ah, bh[0][0], bh[0][1]);
            mma16816(d[mb][1], ah, bh[0][2], bh[0][3]);
            mma16816(d[mb][2], ah, bh[1][0], bh[1][1]);
            mma16816(d[mb][3], ah, bh[1][2], bh[1][3]);
            // HL
            mma16816(d[mb][0], ah, bl[0][0], bl[0][1]);
            mma16816(d[mb][1], ah, bl[0][2], bl[0][3]);
            mma16816(d[mb][2], ah, bl[1][0], bl[1][1]);
            mma16816(d[mb][3], ah, bl[1][2], bl[1][3]);
            // LH
            mma16816(d[mb][0], al, bh[0][0], bh[0][1]);
            mma16816(d[mb][1], al, bh[0][2], bh[0][3]);
            mma16816(d[mb][2], al, bh[1][0], bh[1][1]);
            mma16816(d[mb][3], al, bh[1][2], bh[1][3]);
        }
    }

    #pragma unroll
    for (int mb = 0; mb < 4; ++mb)
        #pragma unroll
        for (int nb = 0; nb < 4; ++nb) {
            int r = c.m0 + mb * 16 + c.g;
            int col = c.n0 + nb * 8 + 2 * c.tig;
            *(float2*)&Cb[r * 128 + col] =
                make_float2(d[mb][nb][0], d[mb][nb][1]);
            *(float2*)&Cb[(r + 8) * 128 + col] =
                make_float2(d[mb][nb][2], d[mb][nb][3]);
        }
}

// Producer (cvt variant): 128 threads cover ALL 4096 float4 granules of a
// 128x128 fp32 tile (4 half-passes of 8 granules/thread). BUG FIX from R10:
// previous version covered only 2048 granules (rows 0-63).
__device__ __forceinline__ void produce_cvt(const float* __restrict__ Ab,
                                            __nv_bfloat16* dst, int p)
{
    #pragma unroll
    for (int half = 0; half < 4; ++half) {
        float4 v[8];
        #pragma unroll
        for (int j = 0; j < 8; ++j) {
            int f = p + 128 * (8 * half + j);           // 0..4095
            v[j] = *(const float4*)&Ab[(f >> 5) * 128 + ((f & 31) << 2)];
        }
        #pragma unroll
        for (int j = 0; j < 8; ++j) {
            int f = p + 128 * (8 * half + j);
            int row = f >> 5, c4 = (f & 31) << 2;
            uint32_t h0, l0, h1, l1;
            cvt_hi_lo2(v[j].x, v[j].y, h0, l0);
            cvt_hi_lo2(v[j].z, v[j].w, h1, l1);
            *(uint2*)&dst[row * WS + c4] = make_uint2(h0, h1);
            *(uint2*)&dst[IMG / 2 + row * WS + c4] = make_uint2(l0, l1);
        }
    }
}

// Producer (pre variant): cp.async both bf16 images (2048 granules of 16B each
// per image; 128 threads x 16).
__device__ __forceinline__ void produce_pre(const __nv_bfloat16* Ahi,
                                            const __nv_bfloat16* Alo,
                                            uint32_t base, int tile, int p)
{
    const char* sh = (const char*)Ahi + (size_t)tile * 32768;
    const char* sl = (const char*)Alo + (size_t)tile * 32768;
    #pragma unroll
    for (int i = 0; i < 16; ++i) {
        int j = p + 128 * i;                 // granule 0..2047
        int row = j >> 4, gg = j & 15;
        uint32_t doff = (uint32_t)(row * WS * 2 + gg * 16);
        cp16(base + doff, sh + row * 256 + gg * 16);
        cp16(base + IMG + doff, sl + row * 256 + gg * 16);
    }
    asm volatile("cp.async.commit_group;");
}

// ---------------------------------------------------------------------------
// tgemm variant 1: A fp32, warp-specialized convert
// ---------------------------------------------------------------------------
__global__ __launch_bounds__(NTHREADS, 1) void tgemm_cvt(
    const float* __restrict__ A,
    const __nv_bfloat16* __restrict__ whi,
    const __nv_bfloat16* __restrict__ wlo,
    float* __restrict__ C)
{
    extern __shared__ __align__(16) uint8_t smem[];
    const int tid = threadIdx.x;
    const uint32_t sb = smem_u32(smem);
    __nv_bfloat16* Abuf = (__nv_bfloat16*)smem;
    const bool is_cons = (tid < 256);

    int tile = blockIdx.x;

    if (is_cons) {
        const uint4* s1 = (const uint4*)whi;
        const uint4* s2 = (const uint4*)wlo;
        #pragma unroll
        for (int i = 0; i < 9; ++i) {
            int j = tid + 256 * i;
            if (j < 2176) {
                cp16(sb + 4 * IMG + 16 * j, s1 + j);
                cp16(sb + 5 * IMG + 16 * j, s2 + j);
            }
        }
        asm volatile("cp.async.commit_group;");
        asm volatile("cp.async.wait_group 0;");
    } else {
        produce_cvt(A + (size_t)tile * 16384, Abuf, tid - 256);
    }
    __syncthreads();

    const MmaCtx ctx = make_ctx(sb, tid);
    int par = 0;

    while (true) {
        const int next = tile + GRID_P;
        const bool have = (next < NT128);

        if (is_cons) {
            do_tile_mma(ctx, sb + (uint32_t)(par * 2 * IMG),
                        C + (size_t)tile * 16384);
        } else if (have) {
            produce_cvt(A + (size_t)next * 16384,
                        Abuf + (par ^ 1) * IMG, tid - 256);
        }

        if (!have) break;
        __syncthreads();
        par ^= 1;
        tile = next;
    }
}

// ---------------------------------------------------------------------------
// tgemm variant 2: A pre-split bf16 images, producers issue cp.async
// ---------------------------------------------------------------------------
__global__ __launch_bounds__(NTHREADS, 1) void tgemm_pre(
    const __nv_bfloat16* __restrict__ Ahi,
    const __nv_bfloat16* __restrict__ Alo,
    const __nv_bfloat16* __restrict__ whi,
    const __nv_bfloat16* __restrict__ wlo,
    float* __restrict__ C)
{
    extern __shared__ __align__(16) uint8_t smem[];
    const int tid = threadIdx.x;
    const uint32_t sb = smem_u32(smem);
    const bool is_cons = (tid < 256);

    int tile = blockIdx.x;

    if (is_cons) {
        const uint4* s1 = (const uint4*)whi;
        const uint4* s2 = (const uint4*)wlo;
        #pragma unroll
        for (int i = 0; i < 9; ++i) {
            int j = tid + 256 * i;
            if (j < 2176) {
                cp16(sb + 4 * IMG + 16 * j, s1 + j);
                cp16(sb + 5 * IMG + 16 * j, s2 + j);
            }
        }
        asm volatile("cp.async.commit_group;");
        asm volatile("cp.async.wait_group 0;");
    } else {
        produce_pre(Ahi, Alo, sb, tile, tid - 256);
        asm volatile("cp.async.wait_group 0;");
    }
    __syncthreads();

    const MmaCtx ctx = make_ctx(sb, tid);
    int par = 0;

    while (true) {
        const int next = tile + GRID_P;
        const bool have = (next < NT128);

        if (is_cons) {
            do_tile_mma(ctx, sb + (uint32_t)(par * 2 * IMG),
                        C + (size_t)tile * 16384);
        } else if (have) {
            produce_pre(Ahi, Alo, sb + (uint32_t)((par ^ 1) * 2 * IMG),
                        next, tid - 256);
            asm volatile("cp.async.wait_group 0;");
        }

        if (!have) break;
        __syncthreads();
        par ^= 1;
        tile = next;
    }
}

// ---------------------------------------------------------------------------
// GAT scatter layer: warp-per-batch. CTA = 8 warps = 8 batches.
// ---------------------------------------------------------------------------
#define GW 8

template <bool LAYER2>
__global__ __launch_bounds__(256) void gat_kernel(
    const float* __restrict__ Hpre,
    const int*   __restrict__ edges,
    const float* __restrict__ a_s,
    const float* __restrict__ a_d,
    const float* __restrict__ bias,
    __nv_bfloat16* __restrict__ out_hi,
    __nv_bfloat16* __restrict__ out_lo,
    float* __restrict__ out_pred,
    float* __restrict__ out_attn)
{
    __shared__ float    s_asn[GW][16], s_adn[GW][16], s_z[GW][16];
    __shared__ unsigned s_mk[GW][16];
    __shared__ float    s_Am[GW][200];
    __shared__ __align__(16) float s_At[GW][196];

    const int tid = threadIdx.x;
    const int w = tid >> 5, lane = tid & 31;
    const int b = blockIdx.x * GW + w;

    #pragma unroll
    for (int i = 0; i < 7; ++i) {
        int j = lane + 32 * i;
        if (j < 196) { s_Am[w][j] = 0.f; if (LAYER2) s_At[w][j] = 0.f; }
    }
    if (lane < 14) { s_mk[w][lane] = 0u; s_z[w][lane] = 0.f; }

    const float* hb = Hpre + (size_t)b * (Nn * Cd);
    float4 v[Nn];
    #pragma unroll
    for (int n = 0; n < Nn; ++n)
        v[n] = *(const float4*)&hb[n * Cd + lane * 4];
    const float4 as4 = *(const float4*)&a_s[lane * 4];
    const float4 ad4 = *(const float4*)&a_d[lane * 4];
    const float4 bi4 = *(const float4*)&bias[lane * 4];

    float pa[Nn], pd[Nn];
    #pragma unroll
    for (int n = 0; n < Nn; ++n) {
        pa[n] = v[n].x * as4.x + v[n].y * as4.y + v[n].z * as4.z + v[n].w * as4.w;
        pd[n] = v[n].x * ad4.x + v[n].y * ad4.y + v[n].z * ad4.z + v[n].w * ad4.w;
    }
    #pragma unroll
    for (int o = 16; o > 0; o >>= 1) {
        #pragma unroll
        for (int n = 0; n < Nn; ++n) {
            pa[n] += __shfl_xor_sync(0xffffffffu, pa[n], o);
            pd[n] += __shfl_xor_sync(0xffffffffu, pd[n], o);
        }
    }
    if (lane == 0) {
        #pragma unroll
        for (int n = 0; n < Nn; ++n) { s_asn[w][n] = pa[n]; s_adn[w][n] = pd[n]; }
    }
    __syncwarp();

    const int* eb = edges + (size_t)b * (Ed * 2);
    int  es_[3], ed_[3];
    float lg_[3], ev_[3];
    bool act[3];
    #pragma unroll
    for (int r = 0; r < 3; ++r) {
        int e = lane + 32 * r;
        act[r] = (e < 78);
        es_[r] = 0; ed_[r] = 0; lg_[r] = 0.f;
        if (act[r]) {
            int s, dd;
            if (e < Ed) { int2 p = *(const int2*)&eb[2 * e]; s = p.x; dd = p.y; }
            else        { s = dd = e - Ed; }
            float x = s_asn[w][s] + s_adn[w][dd];
            x = (x > 0.f) ? x : 0.2f * x;
            es_[r] = s; ed_[r] = dd; lg_[r] = x;
            atomicMax(&s_mk[w][dd], fkey(x));
        }
    }
    __syncwarp();
    #pragma unroll
    for (int r = 0; r < 3; ++r) {
        if (act[r]) {
            float m = kinv(s_mk[w][ed_[r]]);
            ev_[r] = expf(lg_[r] - m);
            atomicAdd(&s_z[w][ed_[r]], ev_[r]);
        }
    }
    __syncwarp();
    #pragma unroll
    for (int r = 0; r < 3; ++r) {
        if (act[r]) {
            float al = ev_[r] / s_z[w][ed_[r]];
            atomicAdd(&s_Am[w][ed_[r] * Nn + es_[r]], al);
            if (LAYER2) s_At[w][es_[r] * Nn + ed_[r]] = al;
        }
    }
    __syncwarp();

    if (!LAYER2) {
        #pragma unroll
        for (int n = 0; n < Nn; ++n) {
            float4 acc = bi4;
            #pragma unroll
            for (int s = 0; s < Nn; ++s) {
                float am = s_Am[w][n * Nn + s];
                acc.x = fmaf(am, v[s].x, acc.x);
                acc.y = fmaf(am, v[s].y, acc.y);
                acc.z = fmaf(am, v[s].z, acc.z);
                acc.w = fmaf(am, v[s].w, acc.w);
            }
            acc.x = fmaxf(acc.x, 0.f); acc.y = fmaxf(acc.y, 0.f);
            acc.z = fmaxf(acc.z, 0.f); acc.w = fmaxf(acc.w, 0.f);
            uint32_t h0, l0, h1, l1;
            cvt_hi_lo2(acc.x, acc.y, h0, l0);
            cvt_hi_lo2(acc.z, acc.w, h1, l1);
            size_t off = (size_t)(b * Nn + n) * 128 + lane * 4;
            *(uint2*)&out_hi[off] = make_uint2(h0, h1);
            *(uint2*)&out_lo[off] = make_uint2(l0, l1);
        }
    } else {
        float p = 0.f;
        #pragma unroll
        for (int n = 0; n < Nn; ++n) {
            float4 acc = bi4;
            #pragma unroll
            for (int s = 0; s < Nn; ++s) {
                float am = s_Am[w][n * Nn + s];
                acc.x = fmaf(am, v[s].x, acc.x);
                acc.y = fmaf(am, v[s].y, acc.y);
                acc.z = fmaf(am, v[s].z, acc.z);
                acc.w = fmaf(am, v[s].w, acc.w);
            }
            float4 wv = *(const float4*)&g_wlp.f[n * Cd + lane * 4];
            p += acc.x * wv.x + acc.y * wv.y + acc.z * wv.z + acc.w * wv.w;
        }
        #pragma unroll
        for (int o = 16; o > 0; o >>= 1)
            p += __shfl_xor_sync(0xffffffffu, p, o);
        if (lane == 0)
            out_pred[b] = 1.f / (1.f + expf(-(p + g_c0)));
        __syncwarp();
        float* ab = out_attn + (size_t)b * (Nn * Nn);
        #pragma unroll
        for (int i = 0; i < 2; ++i) {
            int j = lane + 32 * i;
            if (j < 49)
                *(float4*)&ab[4 * j] = *(const float4*)&s_At[w][4 * j];
        }
    }
}

// ---------------------------------------------------------------------------
extern "C" void kernel_launch(void* const* d_in, const int* in_sizes, int n_in,
                              void* d_out, int out_size)
{
    const float* feature = (const float*)d_in[0];
    const int*   edges   = (const int*)  d_in[1];
    const float* W1      = (const float*)d_in[2];
    const float* a_s1    = (const float*)d_in[3];
    const float* a_d1    = (const float*)d_in[4];
    const float* b1      = (const float*)d_in[5];
    const float* W2      = (const float*)d_in[6];
    const float* a_s2    = (const float*)d_in[7];
    const float* a_d2    = (const float*)d_in[8];
    const float* b2      = (const float*)d_in[9];
    const float* Wl      = (const float*)d_in[10];
    const float* bl      = (const float*)d_in[11];
    const float* Wp      = (const float*)d_in[12];
    const float* bp      = (const float*)d_in[13];

    float* out  = (float*)d_out;
    float* pred = out;            // [B]
    float* attn = out + Bn;       // [B,N,N]

    void *p_buf0, *p_a2h, *p_a2l, *p_w1h, *p_w1l, *p_w2h, *p_w2l;
    cudaGetSymbolAddress(&p_buf0, g_buf0);
    cudaGetSymbolAddress(&p_a2h,  g_a2hi);
    cudaGetSymbolAddress(&p_a2l,  g_a2lo);
    cudaGetSymbolAddress(&p_w1h,  g_w1hi);
    cudaGetSymbolAddress(&p_w1l,  g_w1lo);
    cudaGetSymbolAddress(&p_w2h,  g_w2hi);
    cudaGetSymbolAddress(&p_w2l,  g_w2lo);
    float* buf0 = (float*)p_buf0;
    __nv_bfloat16* a2h = (__nv_bfloat16*)p_a2h;
    __nv_bfloat16* a2l = (__nv_bfloat16*)p_a2l;
    __nv_bfloat16* w1h = (__nv_bfloat16*)p_w1h;
    __nv_bfloat16* w1l = (__nv_bfloat16*)p_w1l;
    __nv_bfloat16* w2h = (__nv_bfloat16*)p_w2h;
    __nv_bfloat16* w2l = (__nv_bfloat16*)p_w2l;

    cudaFuncSetAttribute(tgemm_cvt,
                         cudaFuncAttributeMaxDynamicSharedMemorySize, TG_SMEM);
    cudaFuncSetAttribute(tgemm_pre,
                         cudaFuncAttributeMaxDynamicSharedMemorySize, TG_SMEM);

    // 0. pre-convert weights
    prep_w_kernel<<<128, 128>>>(W1, w1h, w1l);
    prep_w_kernel<<<128, 128>>>(W2, w2h, w2l);

    // 1. collapse prediction head
    wlp_kernel<<<14, 128>>>(Wl, Wp, bl, bp);

    // 2. Hpre1 = feature @ W1  (warp-specialized persistent)
    tgemm_cvt<<<GRID_P, NTHREADS, TG_SMEM>>>(feature, w1h, w1l, buf0);

    // 3. GAT layer 1 -> h1 as pre-split bf16 images
    gat_kernel<false><<<Bn / GW, 256>>>(buf0, edges, a_s1, a_d1, b1,
                                        a2h, a2l, nullptr, nullptr);

    // 4. Hpre2 = h1 @ W2  (warp-specialized persistent, cp.async A)
    tgemm_pre<<<GRID_P, NTHREADS, TG_SMEM>>>(a2h, a2l, w2h, w2l, buf0);

    // 5. GAT layer 2 + attn + fused sigmoid head
    gat_kernel<true><<<Bn / GW, 256>>>(buf0, edges, a_s2, a_d2, b2,
                                       nullptr, nullptr, pred, attn);
}